// round 2
// baseline (speedup 1.0000x reference)
#include <cuda_runtime.h>
#include <math.h>

#define NN   50000
#define FF   48
#define CC   16     // H*C1 with H=1 -> softmax is identically 1, attention vanishes
#define L1   8
#define EMAX 1600000

// ---------------- device scratch (no allocations allowed) ----------------
__device__ __align__(16) float g_y[NN * CC];   // x @ W
__device__ int g_cnt[NN];                      // in-degree histogram
__device__ int g_off[NN + 1];                  // CSR offsets
__device__ int g_pos[NN];                      // scatter cursors
__device__ int g_csr[EMAX];                    // src ids grouped by dst
__device__ int g_is64;

// ---------------- init: zero histogram, detect edge dtype, zero loss ----------------
// int64 edge ids < 50000 => every odd 32-bit word of the first 1024 entries is 0.
__global__ void k_init(const unsigned* __restrict__ ew, float* losss, int n) {
    int i = blockIdx.x * blockDim.x + threadIdx.x;
    if (i < n) g_cnt[i] = 0;
    if (blockIdx.x == 0) {
        __shared__ unsigned any;
        if (threadIdx.x == 0) any = 0u;
        __syncthreads();
        unsigned v = 0u;
        for (int k = threadIdx.x; k < 1024; k += blockDim.x) v |= ew[2 * k + 1];
        if (v) atomicOr(&any, 1u);
        __syncthreads();
        if (threadIdx.x == 0) {
            g_is64 = (any == 0u) ? 1 : 0;
            if (losss) *losss = 0.0f;
        }
    }
}

// ---------------- fused: projection y = x @ W (smem-staged x) + dst histogram ----------------
__global__ void k_proj_hist(const float* __restrict__ x, const float* __restrict__ W,
                            const void* __restrict__ ei, int n, int E, int projBlocks) {
    if ((int)blockIdx.x < projBlocks) {
        __shared__ float sW[FF * CC];     // 3 KB
        __shared__ float sX[16 * FF];     // 3 KB : 16 node rows
        for (int i = threadIdx.x; i < FF * CC; i += blockDim.x) sW[i] = W[i];
        int nodeBase = blockIdx.x * 16;
        for (int i = threadIdx.x; i < 16 * FF; i += blockDim.x) {
            int gidx = nodeBase * FF + i;
            sX[i] = (gidx < n * FF) ? x[gidx] : 0.0f;
        }
        __syncthreads();
        int node = nodeBase + (threadIdx.x >> 4);
        int c    = threadIdx.x & 15;
        if (node < n) {
            const float* xr = &sX[(threadIdx.x >> 4) * FF];
            float acc = 0.0f;
#pragma unroll
            for (int k = 0; k < FF; k++) acc = fmaf(xr[k], sW[k * CC + c], acc);
            g_y[node * CC + c] = acc;
        }
    } else {
        int b = blockIdx.x - projBlocks;
        int base = b * 1024;
        if (g_is64) {
            const long long* dl = (const long long*)ei + E;
#pragma unroll
            for (int k = 0; k < 4; k++) {
                int e = base + k * 256 + threadIdx.x;
                if (e < E) atomicAdd(&g_cnt[(int)dl[e]], 1);
            }
        } else {
            const int* dl = (const int*)ei + E;
#pragma unroll
            for (int k = 0; k < 4; k++) {
                int e = base + k * 256 + threadIdx.x;
                if (e < E) atomicAdd(&g_cnt[dl[e]], 1);
            }
        }
    }
}

// ---------------- single-block exclusive scan over g_cnt -> g_off, g_pos ----------------
__global__ void k_scan(int n, int E) {
    __shared__ int warp_s[32];
    int tid = threadIdx.x;                 // 1024 threads
    int chunk = (n + 1023) / 1024;
    int beg = tid * chunk;
    int end = min(beg + chunk, n);
    int sum = 0;
    for (int i = beg; i < end; i++) sum += g_cnt[i];

    int lane = tid & 31, wid = tid >> 5;
    int v = sum;
#pragma unroll
    for (int o = 1; o < 32; o <<= 1) {
        int t = __shfl_up_sync(0xFFFFFFFFu, v, o);
        if (lane >= o) v += t;
    }
    if (lane == 31) warp_s[wid] = v;
    __syncthreads();
    if (wid == 0) {
        int w = warp_s[lane];
#pragma unroll
        for (int o = 1; o < 32; o <<= 1) {
            int t = __shfl_up_sync(0xFFFFFFFFu, w, o);
            if (lane >= o) w += t;
        }
        warp_s[lane] = w;
    }
    __syncthreads();
    int base = v - sum + (wid ? warp_s[wid - 1] : 0);   // exclusive prefix of this chunk
    int run = base;
    for (int i = beg; i < end; i++) {
        int cv = g_cnt[i];
        g_off[i] = run;
        g_pos[i] = run;
        run += cv;
    }
    if (tid == 0) g_off[n] = E;
}

// ---------------- scatter src ids into CSR buckets ----------------
__global__ void k_scatter(const void* __restrict__ ei, int E) {
    int e = blockIdx.x * blockDim.x + threadIdx.x;
    if (e >= E) return;
    int src, dst;
    if (g_is64) {
        const long long* p = (const long long*)ei;
        src = (int)p[e];
        dst = (int)p[E + e];
    } else {
        const int* p = (const int*)ei;
        src = p[e];
        dst = p[E + e];
    }
    int pos = atomicAdd(&g_pos[dst], 1);
    g_csr[pos] = src;
}

// ---------------- fused gather + mean + bias + relu + MLP + sigmoid + BCE ----------------
// warp per node; half-warp per edge (16 consecutive floats = 64B coalesced read)
__global__ void k_gather_head(const float* __restrict__ bias,
                              const float* __restrict__ l1w,  // [16,8]
                              const float* __restrict__ l1b,
                              const float* __restrict__ ow,   // [8,1]
                              const float* __restrict__ ob,
                              const float* __restrict__ labels,
                              const float* __restrict__ wts,
                              float* __restrict__ pout, float* losss,
                              int n, float inv_n) {
    __shared__ float sl1w[CC * L1], sb[CC], sl1b[L1], sow[L1], sob_s;
    __shared__ float wsum[8];
    if (threadIdx.x < CC * L1) sl1w[threadIdx.x] = l1w[threadIdx.x];
    if (threadIdx.x < CC) sb[threadIdx.x] = bias[threadIdx.x];
    if (threadIdx.x < L1) { sl1b[threadIdx.x] = l1b[threadIdx.x]; sow[threadIdx.x] = ow[threadIdx.x]; }
    if (threadIdx.x == 0) sob_s = ob[0];
    __syncthreads();

    int wid = threadIdx.x >> 5, lane = threadIdx.x & 31;
    int i = blockIdx.x * 8 + wid;
    float term = 0.0f;
    if (i < n) {
        int beg = g_off[i], end = g_off[i + 1];
        int c = lane & 15, half = lane >> 4;
        float acc = 0.0f;
        for (int k = beg + half; k < end; k += 2) {
            int src = __ldg(&g_csr[k]);
            acc += __ldg(&g_y[src * CC + c]);
        }
        acc += __shfl_xor_sync(0xFFFFFFFFu, acc, 16);   // combine halves
        acc += g_y[i * CC + c];                          // self loop
        float deg = (float)(end - beg) + 1.0f;
        float h = fmaxf(fmaf(acc, 1.0f / deg, sb[c]), 0.0f);

        int j = lane & 7;
        float s = sl1b[j];
#pragma unroll
        for (int cc = 0; cc < CC; cc++)
            s = fmaf(__shfl_sync(0xFFFFFFFFu, h, cc), sl1w[cc * L1 + j], s);
        float h2 = fmaxf(s, 0.0f);
        float zp = h2 * sow[j];
        zp += __shfl_xor_sync(0xFFFFFFFFu, zp, 4);
        zp += __shfl_xor_sync(0xFFFFFFFFu, zp, 2);
        zp += __shfl_xor_sync(0xFFFFFFFFu, zp, 1);
        if (lane == 0) {
            float z = zp + sob_s;
            float p = 1.0f / (1.0f + expf(-z));
            pout[i] = p;
            const float eps = 1e-7f;
            float pc = fminf(fmaxf(p, eps), 1.0f - eps);
            float lab = labels[i];
            float bce = -(lab * logf(pc) + (1.0f - lab) * logf(1.0f - pc));
            term = wts[i] * bce * inv_n;
        }
    }
    if (lane == 0) wsum[wid] = term;
    __syncthreads();
    if (threadIdx.x == 0 && losss) {
        float s = 0.0f;
#pragma unroll
        for (int k = 0; k < 8; k++) s += wsum[k];
        atomicAdd(losss, s);
    }
}

// ---------------- launch ----------------
extern "C" void kernel_launch(void* const* d_in, const int* in_sizes, int n_in,
                              void* d_out, int out_size) {
    const float* x      = (const float*)d_in[0];
    const void*  ei     = d_in[1];
    const float* labels = (const float*)d_in[2];
    const float* wts    = (const float*)d_in[3];
    const float* W      = (const float*)d_in[4];
    // d_in[5]=u, d_in[6]=c unused (H=1 softmax == 1)
    const float* bias   = (const float*)d_in[7];
    const float* l1w    = (const float*)d_in[8];
    const float* l1b    = (const float*)d_in[9];
    const float* ow     = (const float*)d_in[10];
    const float* ob     = (const float*)d_in[11];

    int n = in_sizes[0] / FF;
    int E = in_sizes[1] / 2;

    float* out = (float*)d_out;
    int loss_slot = (out_size == n + 1) ? 1 : 0;
    float* pout  = loss_slot ? (out + 1) : out;
    float* losss = loss_slot ? out : (float*)0;

    int projBlocks = (n + 15) / 16;
    int histBlocks = (E + 1023) / 1024;

    k_init<<<(n + 255) / 256, 256>>>((const unsigned*)ei, losss, n);
    k_proj_hist<<<projBlocks + histBlocks, 256>>>(x, W, ei, n, E, projBlocks);
    k_scan<<<1, 1024>>>(n, E);
    k_scatter<<<(E + 255) / 256, 256>>>(ei, E);
    k_gather_head<<<(n + 7) / 8, 256>>>(bias, l1w, l1b, ow, ob, labels, wts,
                                        pout, losss, n, 1.0f / (float)n);
}

// round 3
// speedup vs baseline: 4.2797x; 4.2797x over previous
#include <cuda_runtime.h>
#include <math.h>

#define NN 50000
#define FF 48
#define CC 16     // H*C1 with H=1 -> softmax == 1, attention vanishes
#define L1 8

// ---------------- device scratch ----------------
__device__ __align__(16) float g_y[NN * CC];    // x @ W
__device__ __align__(16) float g_agg[NN * CC];  // segment sum (self loop preloaded)
__device__ float g_deg[NN];
__device__ int   g_is64;

// ---------------- detect edge dtype + zero loss slot ----------------
// int64 node ids < 50000 => every odd 32-bit word of the first 1024 entries is 0.
__global__ void k_detect(const unsigned* __restrict__ ew, float* losss) {
    __shared__ unsigned any;
    if (threadIdx.x == 0) any = 0u;
    __syncthreads();
    unsigned v = 0u;
    for (int i = threadIdx.x; i < 1024; i += blockDim.x) v |= ew[2 * i + 1];
    if (v) atomicOr(&any, 1u);
    __syncthreads();
    if (threadIdx.x == 0) {
        g_is64 = (any == 0u) ? 1 : 0;
        if (losss) *losss = 0.0f;
    }
}

// ---------------- projection y = x @ W (smem-staged), init agg/deg w/ self loop ----------------
__global__ void k_proj(const float* __restrict__ x, const float* __restrict__ W, int n) {
    __shared__ float sW[FF * CC];   // 3 KB
    __shared__ float sX[16 * FF];   // 3 KB: 16 node rows per block
    for (int i = threadIdx.x; i < FF * CC; i += blockDim.x) sW[i] = W[i];
    int nodeBase = blockIdx.x * 16;
    for (int i = threadIdx.x; i < 16 * FF; i += blockDim.x) {
        int g = nodeBase * FF + i;
        sX[i] = (g < n * FF) ? x[g] : 0.0f;
    }
    __syncthreads();
    int node = nodeBase + (threadIdx.x >> 4);
    int c    = threadIdx.x & 15;
    if (node >= n) return;
    const float* xr = &sX[(threadIdx.x >> 4) * FF];
    float acc = 0.0f;
#pragma unroll
    for (int k = 0; k < FF; k++) acc = fmaf(xr[k], sW[k * CC + c], acc);
    g_y[node * CC + c]   = acc;
    g_agg[node * CC + c] = acc;          // self-loop contribution
    if (c == 0) g_deg[node] = 1.0f;      // self-loop degree
}

// ---------------- edge scatter, 4 lanes per edge ----------------
__device__ __forceinline__ void red4(float* addr, float4 v) {
    asm volatile("red.global.add.v4.f32 [%0], {%1,%2,%3,%4};"
                 :: "l"(addr), "f"(v.x), "f"(v.y), "f"(v.z), "f"(v.w) : "memory");
}

__global__ void k_edge(const void* __restrict__ ei, int E) {
    int t = blockIdx.x * blockDim.x + threadIdx.x;
    int e = t >> 2;            // edge id
    int q = t & 3;             // quad lane: which float4 of the 16-float row
    if (e >= E) return;
    int src, dst;
    if (g_is64) {
        const long long* p = (const long long*)ei;
        src = (int)__ldg(&p[e]);
        dst = (int)__ldg(&p[E + e]);
    } else {
        const int* p = (const int*)ei;
        src = __ldg(&p[e]);
        dst = __ldg(&p[E + e]);
    }
    float4 v = __ldg((const float4*)&g_y[src * CC + q * 4]);
    red4(&g_agg[dst * CC + q * 4], v);
    if (q == 0) atomicAdd(&g_deg[dst], 1.0f);
}

// ---------------- head: mean + bias + relu, MLP, sigmoid, weighted BCE ----------------
__global__ void k_head(const float* __restrict__ bias,
                       const float* __restrict__ l1w,  // [16,8]
                       const float* __restrict__ l1b,
                       const float* __restrict__ ow,   // [8,1]
                       const float* __restrict__ ob,
                       const float* __restrict__ labels,
                       const float* __restrict__ wts,
                       float* __restrict__ pout, float* losss,
                       int n, float inv_n) {
    __shared__ float sb[CC], sl1w[CC * L1], sl1b[L1], sow[L1], sob;
    if (threadIdx.x < CC) sb[threadIdx.x] = bias[threadIdx.x];
    if (threadIdx.x < CC * L1) sl1w[threadIdx.x] = l1w[threadIdx.x];
    if (threadIdx.x < L1) { sl1b[threadIdx.x] = l1b[threadIdx.x]; sow[threadIdx.x] = ow[threadIdx.x]; }
    if (threadIdx.x == 0) sob = ob[0];
    __syncthreads();

    int i = blockIdx.x * blockDim.x + threadIdx.x;
    float term = 0.0f;
    if (i < n) {
        float invdeg = 1.0f / fmaxf(g_deg[i], 1.0f);
        const float4* ar = (const float4*)&g_agg[i * CC];
        float4 v0 = ar[0], v1 = ar[1], v2 = ar[2], v3 = ar[3];
        float h[CC] = {v0.x, v0.y, v0.z, v0.w, v1.x, v1.y, v1.z, v1.w,
                       v2.x, v2.y, v2.z, v2.w, v3.x, v3.y, v3.z, v3.w};
#pragma unroll
        for (int c = 0; c < CC; c++) h[c] = fmaxf(fmaf(h[c], invdeg, sb[c]), 0.0f);

        float h2[L1];
#pragma unroll
        for (int j = 0; j < L1; j++) {
            float s = sl1b[j];
#pragma unroll
            for (int c = 0; c < CC; c++) s = fmaf(h[c], sl1w[c * L1 + j], s);
            h2[j] = fmaxf(s, 0.0f);
        }
        float z = sob;
#pragma unroll
        for (int j = 0; j < L1; j++) z = fmaf(h2[j], sow[j], z);
        float p = 1.0f / (1.0f + expf(-z));
        pout[i] = p;

        const float eps = 1e-7f;
        float pc = fminf(fmaxf(p, eps), 1.0f - eps);
        float lab = labels[i];
        float bce = -(lab * logf(pc) + (1.0f - lab) * logf(1.0f - pc));
        term = wts[i] * bce * inv_n;
    }
    // block reduce
#pragma unroll
    for (int off = 16; off > 0; off >>= 1)
        term += __shfl_down_sync(0xFFFFFFFFu, term, off);
    __shared__ float wsum[4];
    int wid = threadIdx.x >> 5, lid = threadIdx.x & 31;
    if (lid == 0) wsum[wid] = term;
    __syncthreads();
    if (threadIdx.x == 0 && losss) {
        float s = 0.0f;
#pragma unroll
        for (int k = 0; k < (int)(blockDim.x >> 5); k++) s += wsum[k];
        atomicAdd(losss, s);
    }
}

// ---------------- launch ----------------
extern "C" void kernel_launch(void* const* d_in, const int* in_sizes, int n_in,
                              void* d_out, int out_size) {
    const float* x      = (const float*)d_in[0];
    const void*  ei     = d_in[1];
    const float* labels = (const float*)d_in[2];
    const float* wts    = (const float*)d_in[3];
    const float* W      = (const float*)d_in[4];
    // d_in[5]=u, d_in[6]=c unused (H=1 softmax == 1)
    const float* bias   = (const float*)d_in[7];
    const float* l1w    = (const float*)d_in[8];
    const float* l1b    = (const float*)d_in[9];
    const float* ow     = (const float*)d_in[10];
    const float* ob     = (const float*)d_in[11];

    int n = in_sizes[0] / FF;
    int E = in_sizes[1] / 2;

    float* out = (float*)d_out;
    int loss_slot = (out_size == n + 1) ? 1 : 0;
    float* pout  = loss_slot ? (out + 1) : out;
    float* losss = loss_slot ? out : (float*)0;

    k_detect<<<1, 256>>>((const unsigned*)ei, losss);
    k_proj<<<(n + 15) / 16, 256>>>(x, W, n);
    long long threads = (long long)E * 4;
    k_edge<<<(int)((threads + 255) / 256), 256>>>(ei, E);
    k_head<<<(n + 127) / 128, 128>>>(bias, l1w, l1b, ow, ob, labels, wts,
                                     pout, losss, n, 1.0f / (float)n);
}